// round 13
// baseline (speedup 1.0000x reference)
#include <cuda_runtime.h>
#include <cuda_fp16.h>

#define NG   2048
#define NB   4
#define CIN  16
#define COUT 32
#define NCTX 256
#define NOUT 1024

#define TPB   1024
#define NWARP 32
#define RSTRIDE 2056            // fp16 elems per r row (2048 + 8 pad)
#define KSPLIT 16
#define KCHUNK (NG / KSPLIT)    // 128 grid points per warp
#define NITER (KCHUNK / 16)     // 8 MMA steps
#define ZROW  20                // padded z row (floats) for conflict-free STS

__device__ __forceinline__ float ex2(float x) {
    float y;
    asm("ex2.approx.ftz.f32 %0, %1;" : "=f"(y) : "f"(x));
    return y;
}
// result = {lo, hi}; PTX cvt.rn.f16x2.f32: first operand -> HIGH half.
__device__ __forceinline__ unsigned cvt_f16x2(float hi, float lo) {
    unsigned r;
    asm("cvt.rn.f16x2.f32 %0, %1, %2;" : "=r"(r) : "f"(hi), "f"(lo));
    return r;
}
__device__ __forceinline__ unsigned long long pack2(float lo, float hi) {
    unsigned long long v;
    asm("mov.b64 %0, {%1, %2};" : "=l"(v) : "f"(lo), "f"(hi));
    return v;
}
__device__ __forceinline__ void unpack2(unsigned long long v, float& lo, float& hi) {
    asm("mov.b64 {%0, %1}, %2;" : "=f"(lo), "=f"(hi) : "l"(v));
}
__device__ __forceinline__ void mul2(unsigned long long& d, unsigned long long a) {
    asm("mul.rn.f32x2 %0, %0, %1;" : "+l"(d) : "l"(a));
}
__device__ __forceinline__ void mma16816(float& d0, float& d1, float& d2, float& d3,
                                         unsigned a0, unsigned a1, unsigned a2, unsigned a3,
                                         unsigned b0, unsigned b1) {
    asm("mma.sync.aligned.m16n8k16.row.col.f32.f16.f16.f32 "
        "{%0,%1,%2,%3}, {%4,%5,%6,%7}, {%8,%9}, {%0,%1,%2,%3};"
        : "+f"(d0), "+f"(d1), "+f"(d2), "+f"(d3)
        : "r"(a0), "r"(a1), "r"(a2), "r"(a3), "r"(b0), "r"(b1));
}

extern __shared__ char smem_raw[];

__global__ __launch_bounds__(TPB, 1)
void conv_decoder_mma(const float* __restrict__ r,
                      const float* __restrict__ xc,
                      const float* __restrict__ xt,
                      const float* __restrict__ sigma,
                      const float* __restrict__ W,
                      const float* __restrict__ bias,
                      float* __restrict__ out) {
    __half* r_h   = (__half*)smem_raw;                       // [CIN][RSTRIDE]
    float*  W_s   = (float*)(smem_raw + CIN * RSTRIDE * 2);  // [CIN*COUT]
    float*  z_prt = W_s + CIN * COUT;                        // [KSPLIT][32][ZROW]
    float*  s_z   = z_prt + KSPLIT * 32 * ZROW;              // [32][CIN]

    __shared__ float s_mn[NWARP], s_mx[NWARP], s_sq[CIN];

    const int b    = blockIdx.y;
    const int tid  = threadIdx.x;
    const int warp = tid >> 5;
    const int lane = tid & 31;

    // ---- Phase A: min/max scan, prescales, stage W and r(fp16) ----------
    {
        float mn = xc[tid & (NB * NCTX - 1)];    // 1024 values, tid covers all
        float mx = mn;
        float4 v = ((const float4*)xt)[tid];     // 4096 = 1024 float4
        mn = fminf(mn, fminf(fminf(v.x, v.y), fminf(v.z, v.w)));
        mx = fmaxf(mx, fmaxf(fmaxf(v.x, v.y), fmaxf(v.z, v.w)));
        #pragma unroll
        for (int s = 16; s > 0; s >>= 1) {
            mn = fminf(mn, __shfl_xor_sync(0xFFFFFFFFu, mn, s));
            mx = fmaxf(mx, __shfl_xor_sync(0xFFFFFFFFu, mx, s));
        }
        if (lane == 0) { s_mn[warp] = mn; s_mx[warp] = mx; }
    }
    if (tid < CIN) s_sq[tid] = 0.84932180028801907f * expf(-sigma[tid]);
    if (tid < CIN * COUT) W_s[tid] = W[tid];
    {
        // 2 warps per channel: warp stages half a row (8 LDG.128 + 8 STS).
        int c = warp >> 1;
        int h = warp & 1;
        const float4* rb4 = (const float4*)(r + ((size_t)b * CIN + c) * NG) + h * 256;
        __half* dst = r_h + c * RSTRIDE + h * 1024;
        #pragma unroll 2
        for (int it = 0; it < 8; it++) {
            float4 v = rb4[it * 32 + lane];
            unsigned p0 = cvt_f16x2(v.y, v.x);
            unsigned p1 = cvt_f16x2(v.w, v.z);
            *(uint2*)(dst + it * 128 + lane * 4) = make_uint2(p0, p1);
        }
    }
    __syncthreads();

    float mn = s_mn[lane];
    float mx = s_mx[lane];
    #pragma unroll
    for (int s = 16; s > 0; s >>= 1) {
        mn = fminf(mn, __shfl_xor_sync(0xFFFFFFFFu, mn, s));
        mx = fmaxf(mx, __shfl_xor_sync(0xFFFFFFFFu, mx, s));
    }
    const float xmin = mn - 0.1f;
    const float step = (mx + 0.1f - xmin) / (float)(NG - 1);

    bool uniform = true;
    #pragma unroll
    for (int c = 1; c < CIN; c++) uniform &= (s_sq[c] == s_sq[0]);

    if (uniform) {
        // ---- HMMA: z(32x16) = wt(32x2048) @ rT(2048x16) ------------------
        // warp = (mt, ks): A generated once, both channel n-tiles per iter.
        const float sq    = s_sq[0];
        const float stepq = step * sq;
        const float xminq = xmin * sq;
        const float S     = 16.0f * stepq;          // scaled k-step stride
        const float qs    = ex2(-2.0f * S * S);
        const unsigned long long qq = pack2(qs, qs);

        const int mt  = warp & 1;           // m-tile (16 targets)
        const int ks  = warp >> 1;          // k-split 0..15
        const int i4  = lane & 3;
        const int grp = lane >> 2;
        const int g0  = ks * KCHUNK;

        const int o_r0 = blockIdx.x * 32 + mt * 16 + grp;
        const float xq0 = xt[b * NOUT + o_r0] * sq;
        const float xq1 = xt[b * NOUT + o_r0 + 8] * sq;

        // Packed weight/update pairs: pw[rr][p] = {w(col_p), w(col_p+1)},
        // col_0 = 2*i4, col_1 = 2*i4+8.
        unsigned long long pw[2][2], pu[2][2];
        #pragma unroll
        for (int p = 0; p < 2; p++) {
            float col = (float)(2 * i4 + 8 * p);
            float pos0 = fmaf((float)g0 + col, stepq, xminq);
            float pos1 = pos0 + stepq;
            float dA0 = pos0 - xq0, dA1 = pos1 - xq0;
            float dB0 = pos0 - xq1, dB1 = pos1 - xq1;
            pw[0][p] = pack2(ex2(-dA0 * dA0), ex2(-dA1 * dA1));
            pw[1][p] = pack2(ex2(-dB0 * dB0), ex2(-dB1 * dB1));
            pu[0][p] = pack2(ex2(-S * (2.0f * dA0 + S)), ex2(-S * (2.0f * dA1 + S)));
            pu[1][p] = pack2(ex2(-S * (2.0f * dB0 + S)), ex2(-S * (2.0f * dB1 + S)));
        }

        const __half* bp0 = r_h + grp * RSTRIDE + g0 + 2 * i4;        // ch 0-7
        const __half* bp1 = bp0 + 8 * RSTRIDE;                        // ch 8-15
        float c0 = 0.f, c1 = 0.f, c2 = 0.f, c3 = 0.f;
        float c4 = 0.f, c5 = 0.f, c6 = 0.f, c7 = 0.f;

        #pragma unroll 1
        for (int j = 0; j < NITER; j++) {
            float lo, hi;
            unpack2(pw[0][0], lo, hi); unsigned A0 = cvt_f16x2(hi, lo);
            unpack2(pw[1][0], lo, hi); unsigned A1 = cvt_f16x2(hi, lo);
            unpack2(pw[0][1], lo, hi); unsigned A2 = cvt_f16x2(hi, lo);
            unpack2(pw[1][1], lo, hi); unsigned A3 = cvt_f16x2(hi, lo);

            unsigned B00 = *(const unsigned*)bp0;
            unsigned B01 = *(const unsigned*)(bp0 + 8);
            unsigned B10 = *(const unsigned*)bp1;
            unsigned B11 = *(const unsigned*)(bp1 + 8);
            bp0 += 16; bp1 += 16;

            mma16816(c0, c1, c2, c3, A0, A1, A2, A3, B00, B01);
            mma16816(c4, c5, c6, c7, A0, A1, A2, A3, B10, B11);

            #pragma unroll
            for (int rr = 0; rr < 2; rr++)
                #pragma unroll
                for (int p = 0; p < 2; p++) {
                    mul2(pw[rr][p], pu[rr][p]);
                    mul2(pu[rr][p], qq);
                }
        }

        // Scatter 16x16 partial into this warp's k-split slot (padded rows).
        {
            float* zp = z_prt + ks * (32 * ZROW) + (mt * 16) * ZROW;
            zp[grp * ZROW + 2 * i4 + 0] = c0;
            zp[grp * ZROW + 2 * i4 + 1] = c1;
            zp[(grp + 8) * ZROW + 2 * i4 + 0] = c2;
            zp[(grp + 8) * ZROW + 2 * i4 + 1] = c3;
            zp[grp * ZROW + 8 + 2 * i4 + 0] = c4;
            zp[grp * ZROW + 8 + 2 * i4 + 1] = c5;
            zp[(grp + 8) * ZROW + 8 + 2 * i4 + 0] = c6;
            zp[(grp + 8) * ZROW + 8 + 2 * i4 + 1] = c7;
        }
        __syncthreads();

        // Combine k-splits: 512 threads, thread = (row, cin), 16 adds.
        if (tid < 512) {
            int row = tid >> 4, c = tid & 15;
            float s = 0.f;
            #pragma unroll
            for (int k = 0; k < KSPLIT; k++)
                s += z_prt[k * (32 * ZROW) + row * ZROW + c];
            s_z[row * CIN + c] = s;
        }
        __syncthreads();

        // Projection: warp = row, lane = cout.
        {
            int row = warp;
            float o = bias[lane];
            #pragma unroll
            for (int c = 0; c < CIN; c++)
                o = fmaf(s_z[row * CIN + c], W_s[c * COUT + lane], o);
            out[((size_t)b * NOUT + blockIdx.x * 32 + row) * COUT + lane] = o;
        }
    } else {
        // ---- Cold path: per-channel length scales (correctness only) -----
        float kneg[CIN];
        #pragma unroll
        for (int c = 0; c < CIN; c++) { float s = s_sq[c]; kneg[c] = -(s * s); }

        int o0 = blockIdx.x * 32 + warp;    // 1 target per warp
        float xv = xt[b * NOUT + o0];
        float a0[CIN];
        #pragma unroll
        for (int c = 0; c < CIN; c++) a0[c] = 0.f;

        const float* rb = r + (size_t)b * CIN * NG;
        #pragma unroll 1
        for (int g = lane; g < NG; g += 32) {
            float gv = fmaf((float)g, step, xmin);
            float dd = gv - xv;
            float d2 = dd * dd;
            #pragma unroll
            for (int c = 0; c < CIN; c++)
                a0[c] = fmaf(rb[c * NG + g], ex2(d2 * kneg[c]), a0[c]);
        }
        #pragma unroll
        for (int s = 16; s > 0; s >>= 1)
            #pragma unroll
            for (int c = 0; c < CIN; c++)
                a0[c] += __shfl_xor_sync(0xFFFFFFFFu, a0[c], s);
        float ov = bias[lane];
        #pragma unroll
        for (int c = 0; c < CIN; c++)
            ov = fmaf(a0[c], W_s[c * COUT + lane], ov);
        out[((size_t)b * NOUT + o0) * COUT + lane] = ov;
    }
}

extern "C" void kernel_launch(void* const* d_in, const int* in_sizes, int n_in,
                              void* d_out, int out_size) {
    const float* r     = (const float*)d_in[0];
    const float* xc    = (const float*)d_in[1];
    // d_in[2] = y_context — unused by the reference computation.
    const float* xt    = (const float*)d_in[3];
    const float* sigma = (const float*)d_in[4];
    const float* W     = (const float*)d_in[5];
    const float* bias  = (const float*)d_in[6];
    float* out = (float*)d_out;

    (void)in_sizes; (void)n_in; (void)out_size;

    const int smem_bytes = CIN * RSTRIDE * 2          // r fp16 (65.8 KB)
                         + CIN * COUT * 4             // W (2 KB)
                         + KSPLIT * 32 * ZROW * 4     // z partials (40 KB)
                         + 32 * CIN * 4;              // reduced z (2 KB)
    cudaFuncSetAttribute(conv_decoder_mma,
                         cudaFuncAttributeMaxDynamicSharedMemorySize, smem_bytes);

    dim3 grid(NOUT / 32, NB);   // (32, 4) = 128 blocks, 1 per SM
    conv_decoder_mma<<<grid, TPB, smem_bytes>>>(r, xc, xt, sigma, W, bias, out);
}

// round 14
// speedup vs baseline: 1.0487x; 1.0487x over previous
#include <cuda_runtime.h>
#include <cuda_fp16.h>

#define NG   2048
#define NB   4
#define CIN  16
#define COUT 32
#define NCTX 256
#define NOUT 1024

#define TPB   512
#define NWARP 16
#define RSTRIDE 2056            // fp16 elems per r row (2048 + 8 pad)
#define KSPLIT 8
#define KCHUNK (NG / KSPLIT)    // 256 grid points per warp
#define NITER (KCHUNK / 16)     // 16 MMA steps
#define ZROW  20                // padded z row (floats) for conflict-free STS

__device__ __forceinline__ float ex2(float x) {
    float y;
    asm("ex2.approx.ftz.f32 %0, %1;" : "=f"(y) : "f"(x));
    return y;
}
// result = {lo, hi}; PTX cvt.rn.f16x2.f32: first operand -> HIGH half.
__device__ __forceinline__ unsigned cvt_f16x2(float hi, float lo) {
    unsigned r;
    asm("cvt.rn.f16x2.f32 %0, %1, %2;" : "=r"(r) : "f"(hi), "f"(lo));
    return r;
}
__device__ __forceinline__ unsigned long long pack2(float lo, float hi) {
    unsigned long long v;
    asm("mov.b64 %0, {%1, %2};" : "=l"(v) : "f"(lo), "f"(hi));
    return v;
}
__device__ __forceinline__ void unpack2(unsigned long long v, float& lo, float& hi) {
    asm("mov.b64 {%0, %1}, %2;" : "=f"(lo), "=f"(hi) : "l"(v));
}
__device__ __forceinline__ void mul2(unsigned long long& d, unsigned long long a) {
    asm("mul.rn.f32x2 %0, %0, %1;" : "+l"(d) : "l"(a));
}
__device__ __forceinline__ void mma16816(float& d0, float& d1, float& d2, float& d3,
                                         unsigned a0, unsigned a1, unsigned a2, unsigned a3,
                                         unsigned b0, unsigned b1) {
    asm("mma.sync.aligned.m16n8k16.row.col.f32.f16.f16.f32 "
        "{%0,%1,%2,%3}, {%4,%5,%6,%7}, {%8,%9}, {%0,%1,%2,%3};"
        : "+f"(d0), "+f"(d1), "+f"(d2), "+f"(d3)
        : "r"(a0), "r"(a1), "r"(a2), "r"(a3), "r"(b0), "r"(b1));
}

extern __shared__ char smem_raw[];

__global__ __launch_bounds__(TPB, 1)
void conv_decoder_mma(const float* __restrict__ r,
                      const float* __restrict__ xc,
                      const float* __restrict__ xt,
                      const float* __restrict__ sigma,
                      const float* __restrict__ W,
                      const float* __restrict__ bias,
                      float* __restrict__ out) {
    __half* r_h   = (__half*)smem_raw;                       // [CIN][RSTRIDE]
    float*  W_s   = (float*)(smem_raw + CIN * RSTRIDE * 2);  // [CIN*COUT]
    float*  z_prt = W_s + CIN * COUT;                        // [KSPLIT][32][ZROW]

    __shared__ float s_mn[NWARP], s_mx[NWARP], s_sq[CIN];

    const int b    = blockIdx.y;
    const int tid  = threadIdx.x;
    const int warp = tid >> 5;
    const int lane = tid & 31;

    // Warp roles for the HMMA path (also used for prefetch below).
    const int mt  = warp & 1;           // m-tile (16 targets)
    const int ks  = warp >> 1;          // k-split 0..7
    const int i4  = lane & 3;
    const int grp = lane >> 2;
    const int g0  = ks * KCHUNK;

    // ---- Phase A: min/max scan, prescales, stage W and r(fp16) ----------
    {
        float mn = fminf(xc[tid], xc[tid + 512]);
        float mx = fmaxf(xc[tid], xc[tid + 512]);
        const float4* xt4 = (const float4*)xt;
        #pragma unroll
        for (int j = 0; j < 2; j++) {
            float4 v = xt4[j * 512 + tid];
            mn = fminf(mn, fminf(fminf(v.x, v.y), fminf(v.z, v.w)));
            mx = fmaxf(mx, fmaxf(fmaxf(v.x, v.y), fmaxf(v.z, v.w)));
        }
        #pragma unroll
        for (int s = 16; s > 0; s >>= 1) {
            mn = fminf(mn, __shfl_xor_sync(0xFFFFFFFFu, mn, s));
            mx = fmaxf(mx, __shfl_xor_sync(0xFFFFFFFFu, mx, s));
        }
        if (lane == 0) { s_mn[warp] = mn; s_mx[warp] = mx; }
    }
    if (tid < CIN) s_sq[tid] = 0.84932180028801907f * expf(-sigma[tid]);
    W_s[tid] = W[tid];                       // CIN*COUT == 512 == TPB
    {
        int c = warp;                        // warp stages channel c
        const float4* rb4 = (const float4*)(r + ((size_t)b * CIN + c) * NG);
        __half* dst = r_h + c * RSTRIDE;
        #pragma unroll
        for (int it = 0; it < 16; it++) {
            float4 v = rb4[it * 32 + lane];
            unsigned p0 = cvt_f16x2(v.y, v.x);
            unsigned p1 = cvt_f16x2(v.w, v.z);
            *(uint2*)(dst + it * 128 + lane * 4) = make_uint2(p0, p1);
        }
    }

    // Prefetch target positions & bias BEFORE the barrier: their global
    // latency overlaps the staging LDGs instead of the post-barrier path.
    const int o_r0 = blockIdx.x * 32 + mt * 16 + grp;
    const float xr0 = xt[b * NOUT + o_r0];
    const float xr1 = xt[b * NOUT + o_r0 + 8];
    const float bv  = bias[lane];

    __syncthreads();

    float mn = (lane < NWARP) ? s_mn[lane] : 1e30f;
    float mx = (lane < NWARP) ? s_mx[lane] : -1e30f;
    #pragma unroll
    for (int s = 16; s > 0; s >>= 1) {
        mn = fminf(mn, __shfl_xor_sync(0xFFFFFFFFu, mn, s));
        mx = fmaxf(mx, __shfl_xor_sync(0xFFFFFFFFu, mx, s));
    }
    const float xmin = mn - 0.1f;
    const float step = (mx + 0.1f - xmin) / (float)(NG - 1);

    bool uniform = true;
    #pragma unroll
    for (int c = 1; c < CIN; c++) uniform &= (s_sq[c] == s_sq[0]);

    if (uniform) {
        // ---- HMMA: z(32x16) = wt(32x2048) @ rT(2048x16) ------------------
        const float sq    = s_sq[0];
        const float stepq = step * sq;
        const float xminq = xmin * sq;
        const float S     = 16.0f * stepq;          // scaled k-step stride
        const float qs    = ex2(-2.0f * S * S);
        const unsigned long long qq = pack2(qs, qs);

        const float xq0 = xr0 * sq;
        const float xq1 = xr1 * sq;

        // Packed weight/update pairs: pw[rr][p] = {w(col_p), w(col_p+1)},
        // col_0 = 2*i4, col_1 = 2*i4+8.
        unsigned long long pw[2][2], pu[2][2];
        #pragma unroll
        for (int p = 0; p < 2; p++) {
            float col = (float)(2 * i4 + 8 * p);
            float pos0 = fmaf((float)g0 + col, stepq, xminq);
            float pos1 = pos0 + stepq;
            float dA0 = pos0 - xq0, dA1 = pos1 - xq0;
            float dB0 = pos0 - xq1, dB1 = pos1 - xq1;
            pw[0][p] = pack2(ex2(-dA0 * dA0), ex2(-dA1 * dA1));
            pw[1][p] = pack2(ex2(-dB0 * dB0), ex2(-dB1 * dB1));
            pu[0][p] = pack2(ex2(-S * (2.0f * dA0 + S)), ex2(-S * (2.0f * dA1 + S)));
            pu[1][p] = pack2(ex2(-S * (2.0f * dB0 + S)), ex2(-S * (2.0f * dB1 + S)));
        }

        const __half* bp0 = r_h + grp * RSTRIDE + g0 + 2 * i4;        // ch 0-7
        const __half* bp1 = bp0 + 8 * RSTRIDE;                        // ch 8-15
        float c0 = 0.f, c1 = 0.f, c2 = 0.f, c3 = 0.f;
        float c4 = 0.f, c5 = 0.f, c6 = 0.f, c7 = 0.f;

        #pragma unroll 1
        for (int j = 0; j < NITER; j++) {
            float lo, hi;
            unpack2(pw[0][0], lo, hi); unsigned A0 = cvt_f16x2(hi, lo);
            unpack2(pw[1][0], lo, hi); unsigned A1 = cvt_f16x2(hi, lo);
            unpack2(pw[0][1], lo, hi); unsigned A2 = cvt_f16x2(hi, lo);
            unpack2(pw[1][1], lo, hi); unsigned A3 = cvt_f16x2(hi, lo);

            unsigned B00 = *(const unsigned*)bp0;
            unsigned B01 = *(const unsigned*)(bp0 + 8);
            unsigned B10 = *(const unsigned*)bp1;
            unsigned B11 = *(const unsigned*)(bp1 + 8);
            bp0 += 16; bp1 += 16;

            mma16816(c0, c1, c2, c3, A0, A1, A2, A3, B00, B01);
            mma16816(c4, c5, c6, c7, A0, A1, A2, A3, B10, B11);

            #pragma unroll
            for (int rr = 0; rr < 2; rr++)
                #pragma unroll
                for (int p = 0; p < 2; p++) {
                    mul2(pw[rr][p], pu[rr][p]);
                    mul2(pu[rr][p], qq);
                }
        }

        // Scatter 16x16 partial into this warp's k-split slot (float2 STS).
        {
            float* zp = z_prt + ks * (32 * ZROW) + (mt * 16) * ZROW;
            *(float2*)(zp + grp * ZROW + 2 * i4)           = make_float2(c0, c1);
            *(float2*)(zp + (grp + 8) * ZROW + 2 * i4)     = make_float2(c2, c3);
            *(float2*)(zp + grp * ZROW + 8 + 2 * i4)       = make_float2(c4, c5);
            *(float2*)(zp + (grp + 8) * ZROW + 8 + 2 * i4) = make_float2(c6, c7);
        }
        __syncthreads();

        // Merged combine + projection (no third barrier, no s_z buffer):
        // lane -> (rr = lane>>4, c = lane&15); warp owns rows 2w, 2w+1.
        {
            const int rr = lane >> 4;
            const int cc = lane & 15;
            const int row = warp * 2 + rr;
            float zsum = 0.f;
            #pragma unroll
            for (int k = 0; k < KSPLIT; k++)
                zsum += z_prt[k * (32 * ZROW) + row * ZROW + cc];

            float o0 = bv, o1 = bv;
            #pragma unroll
            for (int c = 0; c < CIN; c++) {
                float z0 = __shfl_sync(0xFFFFFFFFu, zsum, c);
                float z1 = __shfl_sync(0xFFFFFFFFu, zsum, 16 + c);
                float w = W_s[c * COUT + lane];
                o0 = fmaf(z0, w, o0);
                o1 = fmaf(z1, w, o1);
            }
            size_t obase = ((size_t)b * NOUT + blockIdx.x * 32 + warp * 2) * COUT + lane;
            out[obase]        = o0;
            out[obase + COUT] = o1;
        }
    } else {
        // ---- Cold path: per-channel length scales (correctness only) -----
        float kneg[CIN];
        #pragma unroll
        for (int c = 0; c < CIN; c++) { float s = s_sq[c]; kneg[c] = -(s * s); }

        int o0 = blockIdx.x * 32 + warp * 2;
        float xv0 = xt[b * NOUT + o0];
        float xv1 = xt[b * NOUT + o0 + 1];
        float a0[CIN], a1[CIN];
        #pragma unroll
        for (int c = 0; c < CIN; c++) { a0[c] = 0.f; a1[c] = 0.f; }

        const float* rb = r + (size_t)b * CIN * NG;
        #pragma unroll 1
        for (int g = lane; g < NG; g += 32) {
            float gv = fmaf((float)g, step, xmin);
            float dd0 = gv - xv0, dd1 = gv - xv1;
            float d20 = dd0 * dd0, d21 = dd1 * dd1;
            #pragma unroll
            for (int c = 0; c < CIN; c++) {
                float rv = rb[c * NG + g];
                a0[c] = fmaf(rv, ex2(d20 * kneg[c]), a0[c]);
                a1[c] = fmaf(rv, ex2(d21 * kneg[c]), a1[c]);
            }
        }
        #pragma unroll
        for (int s = 16; s > 0; s >>= 1)
            #pragma unroll
            for (int c = 0; c < CIN; c++) {
                a0[c] += __shfl_xor_sync(0xFFFFFFFFu, a0[c], s);
                a1[c] += __shfl_xor_sync(0xFFFFFFFFu, a1[c], s);
            }
        float o0v = bv, o1v = bv;
        #pragma unroll
        for (int c = 0; c < CIN; c++) {
            o0v = fmaf(a0[c], W_s[c * COUT + lane], o0v);
            o1v = fmaf(a1[c], W_s[c * COUT + lane], o1v);
        }
        out[((size_t)b * NOUT + o0 + 0) * COUT + lane] = o0v;
        out[((size_t)b * NOUT + o0 + 1) * COUT + lane] = o1v;
    }
}

extern "C" void kernel_launch(void* const* d_in, const int* in_sizes, int n_in,
                              void* d_out, int out_size) {
    const float* r     = (const float*)d_in[0];
    const float* xc    = (const float*)d_in[1];
    // d_in[2] = y_context — unused by the reference computation.
    const float* xt    = (const float*)d_in[3];
    const float* sigma = (const float*)d_in[4];
    const float* W     = (const float*)d_in[5];
    const float* bias  = (const float*)d_in[6];
    float* out = (float*)d_out;

    (void)in_sizes; (void)n_in; (void)out_size;

    const int smem_bytes = CIN * RSTRIDE * 2          // r fp16 (65.8 KB)
                         + CIN * COUT * 4             // W (2 KB)
                         + KSPLIT * 32 * ZROW * 4;    // z partials (20.5 KB)
    cudaFuncSetAttribute(conv_decoder_mma,
                         cudaFuncAttributeMaxDynamicSharedMemorySize, smem_bytes);

    dim3 grid(NOUT / 32, NB);   // (32, 4) = 128 blocks
    conv_decoder_mma<<<grid, TPB, smem_bytes>>>(r, xc, xt, sigma, W, bias, out);
}